// round 6
// baseline (speedup 1.0000x reference)
#include <cuda_runtime.h>
#include <cuda_bf16.h>
#include <cstdint>
#include <math.h>

// Problem sizes
#define T_ 256
#define B_ 128
#define D_ 1024
#define H_ 1024
#define O_ 1024
#define MROWS (T_*B_)   // 32768
#define NCOLS (4*H_)    // 4096

// ---------------- device scratch (static, zero-init, no allocs) -------------
__device__ __align__(16) __nv_bfloat16 g_xbf[(size_t)MROWS * D_];        // 64MB
__device__ __align__(16) float         g_Zx[(size_t)MROWS * NCOLS];      // 512MB
__device__ __align__(16) uint2         g_Wxp[32u*64u*16u*32u];           // 8MB  [cn][kt][nt][lane]
__device__ __align__(16) uint2         g_Whp[128u*64u*4u*32u];           // 8MB  [ct][kt][g][lane]
__device__ float                       g_b4[NCOLS];
__device__ __align__(16) __nv_bfloat16 g_h[2][B_*H_];                    // ping-pong h (bf16)
__device__ __align__(16) float         g_hT[B_*H_];                      // final h fp32
__device__ unsigned g_done[128];   // per-CTA step flags (epoch-stamped)
__device__ unsigned g_epoch;       // bumped by k_epoch each run

// ---------------- small PTX helpers ----------------
__device__ __forceinline__ void cpa16(uint32_t saddr, const void* gptr) {
    asm volatile("cp.async.cg.shared.global [%0], [%1], 16;" :: "r"(saddr), "l"(gptr));
}
__device__ __forceinline__ void cpa_commit() { asm volatile("cp.async.commit_group;"); }
__device__ __forceinline__ void cpa_wait0()  { asm volatile("cp.async.wait_group 0;"); }
__device__ __forceinline__ void cpa_wait1()  { asm volatile("cp.async.wait_group 1;"); }
__device__ __forceinline__ void cpa_wait2()  { asm volatile("cp.async.wait_group 2;"); }

__device__ __forceinline__ void ldsm_x4(uint32_t& r0, uint32_t& r1, uint32_t& r2, uint32_t& r3,
                                        uint32_t saddr) {
    asm volatile("ldmatrix.sync.aligned.m8n8.x4.shared.b16 {%0,%1,%2,%3}, [%4];"
                 : "=r"(r0), "=r"(r1), "=r"(r2), "=r"(r3) : "r"(saddr));
}
__device__ __forceinline__ void mma16816(float* d, const uint32_t* a, const uint2 b) {
    asm volatile("mma.sync.aligned.m16n8k16.row.col.f32.bf16.bf16.f32 "
                 "{%0,%1,%2,%3}, {%4,%5,%6,%7}, {%8,%9}, {%0,%1,%2,%3};"
                 : "+f"(d[0]), "+f"(d[1]), "+f"(d[2]), "+f"(d[3])
                 : "r"(a[0]), "r"(a[1]), "r"(a[2]), "r"(a[3]), "r"(b.x), "r"(b.y));
}
__device__ __forceinline__ uint32_t s2u(const void* p) {
    return (uint32_t)__cvta_generic_to_shared(p);
}
__device__ __forceinline__ uint32_t swz(uint32_t byte) {   // 128B swizzle
    return byte ^ ((byte >> 3) & 0x70u);
}
__device__ __forceinline__ float fast_sigmoid(float x) {
    return 1.f / (1.f + __expf(-x));
}
__device__ __forceinline__ float fast_tanh(float x) {
    float e = __expf(-2.f * fabsf(x));
    float t = (1.f - e) / (1.f + e);
    return copysignf(t, x);
}

// ---------------- prep kernels ----------------
__global__ void k_cvt_x(const float* __restrict__ x) {
    size_t idx = (size_t)blockIdx.x * blockDim.x + threadIdx.x;
    if (idx >= (size_t)MROWS * D_ / 4) return;
    float4 v = reinterpret_cast<const float4*>(x)[idx];
    __nv_bfloat162* dst = reinterpret_cast<__nv_bfloat162*>(g_xbf);
    dst[idx * 2 + 0] = __floats2bfloat162_rn(v.x, v.y);
    dst[idx * 2 + 1] = __floats2bfloat162_rn(v.z, v.w);
}

__global__ void k_pack_wx(const float* Wf, const float* Wi, const float* Wg, const float* Wo) {
    unsigned id = blockIdx.x * blockDim.x + threadIdx.x;  // 1048576
    if (id >= 32u*64u*16u*32u) return;
    unsigned lane = id & 31u, nt = (id >> 5) & 15u, kt = (id >> 9) & 63u, cn = id >> 15;
    unsigned c = cn * 128u + nt * 8u + (lane >> 2);
    unsigned g = c >> 10, j = c & 1023u;
    unsigned k0 = kt * 16u + (lane & 3u) * 2u;
    const float* W = (g == 0) ? Wf : (g == 1) ? Wi : (g == 2) ? Wg : Wo;
    const float* base = W + (size_t)j * (D_ + H_) + k0;     // x-part: cols [0,1024)
    __nv_bfloat162 p0 = __floats2bfloat162_rn(base[0], base[1]);
    __nv_bfloat162 p1 = __floats2bfloat162_rn(base[8], base[9]);
    uint2 out;
    out.x = *reinterpret_cast<uint32_t*>(&p0);
    out.y = *reinterpret_cast<uint32_t*>(&p1);
    g_Wxp[id] = out;
}

__global__ void k_pack_wh(const float* Wf, const float* Wi, const float* Wg, const float* Wo) {
    unsigned id = blockIdx.x * blockDim.x + threadIdx.x;  // 1048576
    if (id >= 128u*64u*4u*32u) return;
    unsigned lane = id & 31u, g = (id >> 5) & 3u, kt = (id >> 7) & 63u, ct = id >> 13;
    unsigned j = ct * 8u + (lane >> 2);
    unsigned k0 = kt * 16u + (lane & 3u) * 2u;
    const float* W = (g == 0) ? Wf : (g == 1) ? Wi : (g == 2) ? Wg : Wo;
    const float* base = W + (size_t)j * (D_ + H_) + D_ + k0;  // h-part
    __nv_bfloat162 p0 = __floats2bfloat162_rn(base[0], base[1]);
    __nv_bfloat162 p1 = __floats2bfloat162_rn(base[8], base[9]);
    uint2 out;
    out.x = *reinterpret_cast<uint32_t*>(&p0);
    out.y = *reinterpret_cast<uint32_t*>(&p1);
    g_Whp[id] = out;
}

__global__ void k_pack_b(const float* bf, const float* bi, const float* bg, const float* bo) {
    unsigned i = blockIdx.x * blockDim.x + threadIdx.x;
    if (i >= NCOLS) return;
    unsigned g = i >> 10, j = i & 1023u;
    const float* b = (g == 0) ? bf : (g == 1) ? bi : (g == 2) ? bg : bo;
    g_b4[i] = b[j];
}

__global__ void k_epoch() { g_epoch += 1024u; }

// ---------------- Phase A: Zx = xbf @ Wx4^T + b4 ----------------
__global__ void __launch_bounds__(256) k_gemmA() {
    extern __shared__ char sm[];
    char* As0 = sm;
    char* As1 = sm + 16384;
    uint2* Bs0 = reinterpret_cast<uint2*>(sm + 32768);
    uint2* Bs1 = reinterpret_cast<uint2*>(sm + 49152);
    const int tid = threadIdx.x, lane = tid & 31, w = tid >> 5;
    const int wm = w >> 2, wn = w & 3;
    const int cn = blockIdx.x;           // 0..31
    const int m0 = blockIdx.y * 128;     // 0..32640

    float acc[4][4][4];
#pragma unroll
    for (int a = 0; a < 4; a++)
#pragma unroll
        for (int b = 0; b < 4; b++)
#pragma unroll
            for (int c = 0; c < 4; c++) acc[a][b][c] = 0.f;

    auto load_chunk = [&](int kc, int buf) {
        char* A = buf ? As1 : As0;
        uint2* Bsm = buf ? Bs1 : Bs0;
#pragma unroll
        for (int i = 0; i < 4; i++) {
            int idx = tid + i * 256;
            int row = idx >> 3, seg = idx & 7;
            const void* src = &g_xbf[(size_t)(m0 + row) * D_ + kc * 64 + seg * 8];
            cpa16(s2u(A + swz(row * 128 + seg * 16)), src);
        }
        const uint4* bsrc = reinterpret_cast<const uint4*>(&g_Wxp[((size_t)cn * 64 + kc * 4) * 16 * 32]);
        uint4* bdst = reinterpret_cast<uint4*>(Bsm);
#pragma unroll
        for (int i = 0; i < 4; i++) {
            int idx = tid + i * 256;
            cpa16(s2u(bdst + idx), bsrc + idx);
        }
        cpa_commit();
    };

    load_chunk(0, 0);
    for (int kc = 0; kc < 16; kc++) {
        int buf = kc & 1;
        if (kc < 15) load_chunk(kc + 1, buf ^ 1);
        if (kc < 15) cpa_wait1(); else cpa_wait0();
        __syncthreads();
        char* A = buf ? As1 : As0;
        uint2* Bsm = buf ? Bs1 : Bs0;
#pragma unroll
        for (int ktl = 0; ktl < 4; ktl++) {
            uint32_t afr[4][4];
#pragma unroll
            for (int mt = 0; mt < 4; mt++) {
                int r = wm * 64 + mt * 16 + (lane & 15);
                int ch = ktl * 16 + ((lane >> 4) << 3);
                ldsm_x4(afr[mt][0], afr[mt][1], afr[mt][2], afr[mt][3],
                        s2u(A + swz(r * 128 + ch * 2)));
            }
            uint2 bfr[4];
#pragma unroll
            for (int nt = 0; nt < 4; nt++)
                bfr[nt] = Bsm[((ktl) * 16 + wn * 4 + nt) * 32 + lane];
#pragma unroll
            for (int mt = 0; mt < 4; mt++)
#pragma unroll
                for (int nt = 0; nt < 4; nt++)
                    mma16816(acc[mt][nt], afr[mt], bfr[nt]);
        }
        __syncthreads();
    }
#pragma unroll
    for (int mt = 0; mt < 4; mt++) {
        int r0 = m0 + wm * 64 + mt * 16 + (lane >> 2);
#pragma unroll
        for (int nt = 0; nt < 4; nt++) {
            int c0 = cn * 128 + wn * 32 + nt * 8 + (lane & 3) * 2;
            float b0 = g_b4[c0], b1 = g_b4[c0 + 1];
            float2 v0 = make_float2(acc[mt][nt][0] + b0, acc[mt][nt][1] + b1);
            float2 v1 = make_float2(acc[mt][nt][2] + b0, acc[mt][nt][3] + b1);
            *reinterpret_cast<float2*>(&g_Zx[(size_t)r0 * NCOLS + c0]) = v0;
            *reinterpret_cast<float2*>(&g_Zx[(size_t)(r0 + 8) * NCOLS + c0]) = v1;
        }
    }
}

// ---------------- Phase B: persistent recurrent kernel ----------------
// 128 CTAs. CTA ct owns hidden units [ct*8, ct*8+8) x 4 gates x 128 batches.
// Warp tiling: wm = w>>1 (4 m-tiles of 32 rows), wn = w&1 (2 gates each).
// smem: WhS 64KB parked + As[4][16KB] ring (64KB) + zs[128*32]f32 (16KB)
__global__ void __launch_bounds__(256) k_lstm() {
    extern __shared__ char sm[];
    uint2* WhS = reinterpret_cast<uint2*>(sm);               // 64KB
    char*  As  = sm + 65536;                                  // 4 x 16KB ring
    float* zs  = reinterpret_cast<float*>(sm + 131072);       // 16KB
    const int ct = blockIdx.x;
    const int tid = threadIdx.x, lane = tid & 31, w = tid >> 5;
    const int wm = w >> 1, wn = w & 1;
    const int half = tid >> 7;           // 0: rows 0-63, 1: rows 64-127
    const int lidx = tid & 127;
    const unsigned E = g_epoch;

    // park Wh fragments (64KB contiguous)
    {
        const uint4* src = reinterpret_cast<const uint4*>(&g_Whp[(size_t)ct * 64 * 4 * 32]);
        uint4* dst = reinterpret_cast<uint4*>(WhS);
        for (int i = tid; i < 4096; i += 256) dst[i] = src[i];
    }
    float cst[4] = {0.f, 0.f, 0.f, 0.f};

    // prefetch Zx for t=0
    float zx[4][4];
#pragma unroll
    for (int i = 0; i < 4; i++) {
        int cell = tid + i * 256;
        int b = cell >> 3, jl = cell & 7;
        const float* zp = &g_Zx[(size_t)b * NCOLS + ct * 8 + jl];
        zx[i][0] = __ldcs(zp); zx[i][1] = __ldcs(zp + 1024);
        zx[i][2] = __ldcs(zp + 2048); zx[i][3] = __ldcs(zp + 3072);
    }
    __syncthreads();

    for (int t = 0; t < T_; t++) {
        if (t > 0) {
            // wait for all CTAs to finish step t-1 (flag >= E + t)
            if (tid < 128) {
                volatile unsigned* f = &g_done[tid];
                unsigned target = E + (unsigned)t;
                while ((int)(*f - target) < 0) __nanosleep(32);
                __threadfence();
            }
        }
        __syncthreads();

        float acc[2][2][4];
#pragma unroll
        for (int a = 0; a < 2; a++)
#pragma unroll
            for (int b = 0; b < 2; b++)
#pragma unroll
                for (int c = 0; c < 4; c++) acc[a][b][c] = 0.f;

        if (t > 0) {
            const __nv_bfloat16* hsrc = g_h[(t + 1) & 1];
            auto load_chunk = [&](int kc) {
                char* A = As + (size_t)(kc & 3) * 16384;
#pragma unroll
                for (int i = 0; i < 4; i++) {
                    int idx = lidx + i * 128;
                    int row = half * 64 + (idx >> 3), seg = idx & 7;
                    const void* src = &hsrc[(size_t)row * H_ + kc * 64 + seg * 8];
                    cpa16(s2u(A + swz(row * 128 + seg * 16)), src);
                }
            };
            // prologue: chunks 0,1 in flight
            load_chunk(0); cpa_commit();
            load_chunk(1); cpa_commit();
            for (int kc = 0; kc < 16; kc++) {
                if (kc + 2 < 16) load_chunk(kc + 2);
                cpa_commit();          // always commit (group accounting)
                cpa_wait2();           // chunk kc complete
                asm volatile("bar.sync %0, 128;" :: "r"(1 + half) : "memory");
                char* A = As + (size_t)(kc & 3) * 16384;
#pragma unroll
                for (int ktl = 0; ktl < 4; ktl++) {
                    uint2 bfr[2];
#pragma unroll
                    for (int nt = 0; nt < 2; nt++)
                        bfr[nt] = WhS[(((kc * 4 + ktl) * 4) + wn * 2 + nt) * 32 + lane];
#pragma unroll
                    for (int mt = 0; mt < 2; mt++) {
                        int r = wm * 32 + mt * 16 + (lane & 15);
                        int ch = ktl * 16 + ((lane >> 4) << 3);
                        uint32_t afr[4];
                        ldsm_x4(afr[0], afr[1], afr[2], afr[3],
                                s2u(A + swz(r * 128 + ch * 2)));
                        mma16816(acc[mt][0], afr, bfr[0]);
                        mma16816(acc[mt][1], afr, bfr[1]);
                    }
                }
            }
            // write z tile to smem and exchange
#pragma unroll
            for (int mt = 0; mt < 2; mt++) {
                int r = wm * 32 + mt * 16 + (lane >> 2);
#pragma unroll
                for (int nt = 0; nt < 2; nt++) {
                    int cl = (wn * 2 + nt) * 8 + (lane & 3) * 2;
                    zs[r * 32 + cl]           = acc[mt][nt][0];
                    zs[r * 32 + cl + 1]       = acc[mt][nt][1];
                    zs[(r + 8) * 32 + cl]     = acc[mt][nt][2];
                    zs[(r + 8) * 32 + cl + 1] = acc[mt][nt][3];
                }
            }
            __syncthreads();
        }

        // gate math + h write
        __nv_bfloat16* hdst = g_h[t & 1];
        const bool last = (t == T_ - 1);
#pragma unroll
        for (int i = 0; i < 4; i++) {
            int cell = tid + i * 256;
            int b = cell >> 3, jl = cell & 7;
            float zi = zx[i][0], zf = zx[i][1], zg = zx[i][2], zo = zx[i][3];
            if (t > 0) {
                zi += zs[b * 32 + 0 + jl];
                zf += zs[b * 32 + 8 + jl];
                zg += zs[b * 32 + 16 + jl];
                zo += zs[b * 32 + 24 + jl];
            }
            float it = fast_sigmoid(zi);
            float ft = fast_sigmoid(zf);
            float gt = fast_tanh(zg);
            float ot = fast_sigmoid(zo);
            cst[i] = ft * cst[i] + it * gt;
            float hh = ot * fast_tanh(cst[i]);
            if (!last) hdst[(size_t)b * H_ + ct * 8 + jl] = __float2bfloat16(hh);
            else       g_hT[(size_t)b * H_ + ct * 8 + jl] = hh;
        }

        if (!last) {
            __threadfence();
            __syncthreads();
            if (tid == 0) {
                // release flag: step t complete
                *(volatile unsigned*)&g_done[ct] = E + (unsigned)t + 1u;
            }
            // prefetch Zx for step t+1 (overlaps with poll wait)
#pragma unroll
            for (int i = 0; i < 4; i++) {
                int cell = tid + i * 256;
                int b = cell >> 3, jl = cell & 7;
                const float* zp = &g_Zx[(size_t)((t + 1) * B_ + b) * NCOLS + ct * 8 + jl];
                zx[i][0] = __ldcs(zp); zx[i][1] = __ldcs(zp + 1024);
                zx[i][2] = __ldcs(zp + 2048); zx[i][3] = __ldcs(zp + 3072);
            }
        }
    }
}

// ---------------- Phase C: logits + log_softmax ----------------
__global__ void __launch_bounds__(256) k_logits(const float* __restrict__ Wout,
                                                const float* __restrict__ bout,
                                                float* __restrict__ out) {
    __shared__ float hs[1024];
    __shared__ float ls[1024];
    __shared__ float red[16];
    const int b = blockIdx.x, tid = threadIdx.x, lane = tid & 31, w = tid >> 5;
    for (int i = tid; i < 1024; i += 256) hs[i] = g_hT[(size_t)b * H_ + i];
    __syncthreads();
    for (int k = 0; k < 4; k++) {
        int o = tid + k * 256;
        const float4* wr = reinterpret_cast<const float4*>(Wout + (size_t)o * H_);
        float s = 0.f;
#pragma unroll 4
        for (int h4 = 0; h4 < 256; h4++) {
            float4 wv = wr[h4];
            s += hs[h4 * 4 + 0] * wv.x + hs[h4 * 4 + 1] * wv.y +
                 hs[h4 * 4 + 2] * wv.z + hs[h4 * 4 + 3] * wv.w;
        }
        ls[o] = s + bout[o];
    }
    __syncthreads();
    float lm = -1e30f;
    for (int i = tid; i < 1024; i += 256) lm = fmaxf(lm, ls[i]);
#pragma unroll
    for (int off = 16; off; off >>= 1) lm = fmaxf(lm, __shfl_xor_sync(0xffffffffu, lm, off));
    if (lane == 0) red[w] = lm;
    __syncthreads();
    float m = red[0];
#pragma unroll
    for (int j = 1; j < 8; j++) m = fmaxf(m, red[j]);
    float se = 0.f;
    for (int i = tid; i < 1024; i += 256) se += expf(ls[i] - m);
#pragma unroll
    for (int off = 16; off; off >>= 1) se += __shfl_xor_sync(0xffffffffu, se, off);
    if (lane == 0) red[8 + w] = se;
    __syncthreads();
    float tot = 0.f;
#pragma unroll
    for (int j = 0; j < 8; j++) tot += red[8 + j];
    float lse = logf(tot);
    for (int i = tid; i < 1024; i += 256)
        out[(size_t)b * O_ + i] = ls[i] - m - lse;
}

// ---------------- launch ----------------
extern "C" void kernel_launch(void* const* d_in, const int* in_sizes, int n_in,
                              void* d_out, int out_size) {
    const float* x    = (const float*)d_in[0];
    const float* Wf   = (const float*)d_in[1];
    const float* bf   = (const float*)d_in[2];
    const float* Wi   = (const float*)d_in[3];
    const float* bi   = (const float*)d_in[4];
    const float* Wg   = (const float*)d_in[5];
    const float* bg   = (const float*)d_in[6];
    const float* Wo   = (const float*)d_in[7];
    const float* bo   = (const float*)d_in[8];
    const float* Wout = (const float*)d_in[9];
    const float* bout = (const float*)d_in[10];
    float* out = (float*)d_out;

    cudaFuncSetAttribute(k_gemmA, cudaFuncAttributeMaxDynamicSharedMemorySize, 65536);
    cudaFuncSetAttribute(k_lstm,  cudaFuncAttributeMaxDynamicSharedMemorySize, 147456);

    k_cvt_x<<<(MROWS * D_ / 4 + 511) / 512, 512>>>(x);
    k_pack_wx<<<(32 * 64 * 16 * 32) / 256, 256>>>(Wf, Wi, Wg, Wo);
    k_pack_wh<<<(128 * 64 * 4 * 32) / 256, 256>>>(Wf, Wi, Wg, Wo);
    k_pack_b<<<NCOLS / 256, 256>>>(bf, bi, bg, bo);
    dim3 gA(32, 256);
    k_gemmA<<<gA, 256, 65536>>>();
    k_epoch<<<1, 1>>>();
    k_lstm<<<128, 256, 147456>>>();
    k_logits<<<B_, 256>>>(Wout, bout, out);
}

// round 7
// speedup vs baseline: 1.0705x; 1.0705x over previous
#include <cuda_runtime.h>
#include <cuda_bf16.h>
#include <cstdint>
#include <math.h>

// Problem sizes
#define T_ 256
#define B_ 128
#define D_ 1024
#define H_ 1024
#define O_ 1024
#define MROWS (T_*B_)   // 32768
#define NCOLS (4*H_)    // 4096

// ---------------- device scratch (static, zero-init, no allocs) -------------
__device__ __align__(16) __nv_bfloat16 g_xbf[(size_t)MROWS * D_];        // 64MB
__device__ __align__(16) float         g_Zx[(size_t)MROWS * NCOLS];      // 512MB
__device__ __align__(16) uint2         g_Wxp[32u*64u*16u*32u];           // 8MB  [cn][kt][nt][lane]
__device__ __align__(16) uint2         g_Whp[128u*64u*4u*32u];           // 8MB  [ct][kt][g][lane]
__device__ float                       g_b4[NCOLS];
__device__ __align__(16) __nv_bfloat16 g_h[2][B_*H_];                    // ping-pong h (bf16)
__device__ __align__(16) float         g_hT[B_*H_];                      // final h fp32
__device__ unsigned g_gcnt[16];    // per-group (8 CTAs) step counters

// ---------------- small PTX helpers ----------------
__device__ __forceinline__ void cpa16(uint32_t saddr, const void* gptr) {
    asm volatile("cp.async.cg.shared.global [%0], [%1], 16;" :: "r"(saddr), "l"(gptr));
}
__device__ __forceinline__ void cpa_commit() { asm volatile("cp.async.commit_group;"); }
__device__ __forceinline__ void cpa_wait0()  { asm volatile("cp.async.wait_group 0;"); }
__device__ __forceinline__ void cpa_wait1()  { asm volatile("cp.async.wait_group 1;"); }
__device__ __forceinline__ void cpa_wait2()  { asm volatile("cp.async.wait_group 2;"); }

__device__ __forceinline__ void ldsm_x4(uint32_t& r0, uint32_t& r1, uint32_t& r2, uint32_t& r3,
                                        uint32_t saddr) {
    asm volatile("ldmatrix.sync.aligned.m8n8.x4.shared.b16 {%0,%1,%2,%3}, [%4];"
                 : "=r"(r0), "=r"(r1), "=r"(r2), "=r"(r3) : "r"(saddr));
}
__device__ __forceinline__ void mma16816(float* d, const uint32_t* a, const uint2 b) {
    asm volatile("mma.sync.aligned.m16n8k16.row.col.f32.bf16.bf16.f32 "
                 "{%0,%1,%2,%3}, {%4,%5,%6,%7}, {%8,%9}, {%0,%1,%2,%3};"
                 : "+f"(d[0]), "+f"(d[1]), "+f"(d[2]), "+f"(d[3])
                 : "r"(a[0]), "r"(a[1]), "r"(a[2]), "r"(a[3]), "r"(b.x), "r"(b.y));
}
__device__ __forceinline__ uint32_t s2u(const void* p) {
    return (uint32_t)__cvta_generic_to_shared(p);
}
__device__ __forceinline__ uint32_t swz(uint32_t byte) {   // 128B swizzle
    return byte ^ ((byte >> 3) & 0x70u);
}
__device__ __forceinline__ float fast_sigmoid(float x) {
    return 1.f / (1.f + __expf(-x));
}
__device__ __forceinline__ float fast_tanh(float x) {
    float e = __expf(-2.f * fabsf(x));
    float t = (1.f - e) / (1.f + e);
    return copysignf(t, x);
}

// ---------------- prep kernels ----------------
__global__ void k_cvt_x(const float* __restrict__ x) {
    size_t idx = (size_t)blockIdx.x * blockDim.x + threadIdx.x;
    if (idx >= (size_t)MROWS * D_ / 4) return;
    float4 v = reinterpret_cast<const float4*>(x)[idx];
    __nv_bfloat162* dst = reinterpret_cast<__nv_bfloat162*>(g_xbf);
    dst[idx * 2 + 0] = __floats2bfloat162_rn(v.x, v.y);
    dst[idx * 2 + 1] = __floats2bfloat162_rn(v.z, v.w);
}

__global__ void k_pack_wx(const float* Wf, const float* Wi, const float* Wg, const float* Wo) {
    unsigned id = blockIdx.x * blockDim.x + threadIdx.x;  // 1048576
    if (id >= 32u*64u*16u*32u) return;
    unsigned lane = id & 31u, nt = (id >> 5) & 15u, kt = (id >> 9) & 63u, cn = id >> 15;
    unsigned c = cn * 128u + nt * 8u + (lane >> 2);
    unsigned g = c >> 10, j = c & 1023u;
    unsigned k0 = kt * 16u + (lane & 3u) * 2u;
    const float* W = (g == 0) ? Wf : (g == 1) ? Wi : (g == 2) ? Wg : Wo;
    const float* base = W + (size_t)j * (D_ + H_) + k0;     // x-part: cols [0,1024)
    __nv_bfloat162 p0 = __floats2bfloat162_rn(base[0], base[1]);
    __nv_bfloat162 p1 = __floats2bfloat162_rn(base[8], base[9]);
    uint2 out;
    out.x = *reinterpret_cast<uint32_t*>(&p0);
    out.y = *reinterpret_cast<uint32_t*>(&p1);
    g_Wxp[id] = out;
}

__global__ void k_pack_wh(const float* Wf, const float* Wi, const float* Wg, const float* Wo) {
    unsigned id = blockIdx.x * blockDim.x + threadIdx.x;  // 1048576
    if (id >= 128u*64u*4u*32u) return;
    unsigned lane = id & 31u, g = (id >> 5) & 3u, kt = (id >> 7) & 63u, ct = id >> 13;
    unsigned j = ct * 8u + (lane >> 2);
    unsigned k0 = kt * 16u + (lane & 3u) * 2u;
    const float* W = (g == 0) ? Wf : (g == 1) ? Wi : (g == 2) ? Wg : Wo;
    const float* base = W + (size_t)j * (D_ + H_) + D_ + k0;  // h-part
    __nv_bfloat162 p0 = __floats2bfloat162_rn(base[0], base[1]);
    __nv_bfloat162 p1 = __floats2bfloat162_rn(base[8], base[9]);
    uint2 out;
    out.x = *reinterpret_cast<uint32_t*>(&p0);
    out.y = *reinterpret_cast<uint32_t*>(&p1);
    g_Whp[id] = out;
}

__global__ void k_pack_b(const float* bf, const float* bi, const float* bg, const float* bo) {
    unsigned i = blockIdx.x * blockDim.x + threadIdx.x;
    if (i >= NCOLS) return;
    unsigned g = i >> 10, j = i & 1023u;
    const float* b = (g == 0) ? bf : (g == 1) ? bi : (g == 2) ? bg : bo;
    g_b4[i] = b[j];
}

__global__ void k_epoch() {
    if (threadIdx.x < 16) g_gcnt[threadIdx.x] = 0u;
}

// ---------------- Phase A: Zx = xbf @ Wx4^T + b4 ----------------
// CTA tile 128x128, K chunks of 64. 3-stage ring (32KB/stage = A 16KB + B 16KB),
// one __syncthreads per chunk, issue-after-compute.
__global__ void __launch_bounds__(256) k_gemmA() {
    extern __shared__ char sm[];
    const int tid = threadIdx.x, lane = tid & 31, w = tid >> 5;
    const int wm = w >> 2, wn = w & 3;
    const int cn = blockIdx.x;           // 0..31
    const int m0 = blockIdx.y * 128;     // 0..32640

    float acc[4][4][4];
#pragma unroll
    for (int a = 0; a < 4; a++)
#pragma unroll
        for (int b = 0; b < 4; b++)
#pragma unroll
            for (int c = 0; c < 4; c++) acc[a][b][c] = 0.f;

    auto load_chunk = [&](int kc) {
        int st = kc % 3;
        char* A = sm + (size_t)st * 32768;
        uint4* bdst = reinterpret_cast<uint4*>(sm + (size_t)st * 32768 + 16384);
#pragma unroll
        for (int i = 0; i < 4; i++) {
            int idx = tid + i * 256;
            int row = idx >> 3, seg = idx & 7;
            const void* src = &g_xbf[(size_t)(m0 + row) * D_ + kc * 64 + seg * 8];
            cpa16(s2u(A + swz(row * 128 + seg * 16)), src);
        }
        const uint4* bsrc = reinterpret_cast<const uint4*>(&g_Wxp[((size_t)cn * 64 + kc * 4) * 16 * 32]);
#pragma unroll
        for (int i = 0; i < 4; i++) {
            int idx = tid + i * 256;
            cpa16(s2u(bdst + idx), bsrc + idx);
        }
        cpa_commit();
    };

    load_chunk(0);
    load_chunk(1);
    for (int kc = 0; kc < 16; kc++) {
        if (kc < 15) cpa_wait1(); else cpa_wait0();
        __syncthreads();
        int st = kc % 3;
        char* A = sm + (size_t)st * 32768;
        uint2* Bsm = reinterpret_cast<uint2*>(sm + (size_t)st * 32768 + 16384);
#pragma unroll
        for (int ktl = 0; ktl < 4; ktl++) {
            uint32_t afr[4][4];
#pragma unroll
            for (int mt = 0; mt < 4; mt++) {
                int r = wm * 64 + mt * 16 + (lane & 15);
                int ch = ktl * 16 + ((lane >> 4) << 3);
                ldsm_x4(afr[mt][0], afr[mt][1], afr[mt][2], afr[mt][3],
                        s2u(A + swz(r * 128 + ch * 2)));
            }
            uint2 bfr[4];
#pragma unroll
            for (int nt = 0; nt < 4; nt++)
                bfr[nt] = Bsm[((ktl) * 16 + wn * 4 + nt) * 32 + lane];
#pragma unroll
            for (int mt = 0; mt < 4; mt++)
#pragma unroll
                for (int nt = 0; nt < 4; nt++)
                    mma16816(acc[mt][nt], afr[mt], bfr[nt]);
        }
        if (kc + 2 < 16) load_chunk(kc + 2);
    }
#pragma unroll
    for (int mt = 0; mt < 4; mt++) {
        int r0 = m0 + wm * 64 + mt * 16 + (lane >> 2);
#pragma unroll
        for (int nt = 0; nt < 4; nt++) {
            int c0 = cn * 128 + wn * 32 + nt * 8 + (lane & 3) * 2;
            float b0 = g_b4[c0], b1 = g_b4[c0 + 1];
            float2 v0 = make_float2(acc[mt][nt][0] + b0, acc[mt][nt][1] + b1);
            float2 v1 = make_float2(acc[mt][nt][2] + b0, acc[mt][nt][3] + b1);
            *reinterpret_cast<float2*>(&g_Zx[(size_t)r0 * NCOLS + c0]) = v0;
            *reinterpret_cast<float2*>(&g_Zx[(size_t)(r0 + 8) * NCOLS + c0]) = v1;
        }
    }
}

// ---------------- Phase B: persistent recurrent kernel ----------------
// 128 CTAs. CTA ct owns hidden units [ct*8, ct*8+8) x 4 gates x 128 batches.
// Fine-grained sync: 16 group counters (8 producer CTAs each). Consumer polls
// group kc's counter >= 8t right before issuing chunk kc's cp.async.
// smem: WhS 64KB parked + As[4][16KB] ring (64KB) + zs[128*32]f32 (16KB)
__global__ void __launch_bounds__(256) k_lstm() {
    extern __shared__ char sm[];
    uint2* WhS = reinterpret_cast<uint2*>(sm);               // 64KB
    char*  As  = sm + 65536;                                  // 4 x 16KB ring
    float* zs  = reinterpret_cast<float*>(sm + 131072);       // 16KB
    const int ct = blockIdx.x;
    const int tid = threadIdx.x, lane = tid & 31, w = tid >> 5;
    const int wm = w >> 1, wn = w & 1;
    const int half = tid >> 7;           // 0: rows 0-63, 1: rows 64-127
    const int lidx = tid & 127;

    // park Wh fragments (64KB contiguous)
    {
        const uint4* src = reinterpret_cast<const uint4*>(&g_Whp[(size_t)ct * 64 * 4 * 32]);
        uint4* dst = reinterpret_cast<uint4*>(WhS);
        for (int i = tid; i < 4096; i += 256) dst[i] = src[i];
    }
    float cst[4] = {0.f, 0.f, 0.f, 0.f};

    // prefetch Zx for t=0
    float zx[4][4];
#pragma unroll
    for (int i = 0; i < 4; i++) {
        int cell = tid + i * 256;
        int b = cell >> 3, jl = cell & 7;
        const float* zp = &g_Zx[(size_t)b * NCOLS + ct * 8 + jl];
        zx[i][0] = __ldcs(zp); zx[i][1] = __ldcs(zp + 1024);
        zx[i][2] = __ldcs(zp + 2048); zx[i][3] = __ldcs(zp + 3072);
    }
    __syncthreads();

    for (int t = 0; t < T_; t++) {
        const bool last = (t == T_ - 1);

        if (t > 0) {
            const __nv_bfloat16* hsrc = g_h[(t + 1) & 1];
            const unsigned target = 8u * (unsigned)t;
            auto poll = [&](int g) {
                volatile unsigned* p = &g_gcnt[g];
                while ((int)(*p - target) < 0) { }
            };
            auto load_chunk = [&](int kc) {
                char* A = As + (size_t)(kc & 3) * 16384;
#pragma unroll
                for (int i = 0; i < 4; i++) {
                    int idx = lidx + i * 128;
                    int row = half * 64 + (idx >> 3), seg = idx & 7;
                    const void* src = &hsrc[(size_t)row * H_ + kc * 64 + seg * 8];
                    cpa16(s2u(A + swz(row * 128 + seg * 16)), src);
                }
                cpa_commit();
            };
            poll(0); load_chunk(0);
            poll(1); load_chunk(1);
            poll(2); load_chunk(2);
            float acc[2][2][4];
#pragma unroll
            for (int a = 0; a < 2; a++)
#pragma unroll
                for (int b = 0; b < 2; b++)
#pragma unroll
                    for (int c = 0; c < 4; c++) acc[a][b][c] = 0.f;

            for (int kc = 0; kc < 16; kc++) {
                if (kc <= 13) cpa_wait2();
                else if (kc == 14) cpa_wait1();
                else cpa_wait0();
                asm volatile("bar.sync %0, 128;" :: "r"(1 + half) : "memory");
                char* A = As + (size_t)(kc & 3) * 16384;
#pragma unroll
                for (int ktl = 0; ktl < 4; ktl++) {
                    uint2 bfr[2];
#pragma unroll
                    for (int nt = 0; nt < 2; nt++)
                        bfr[nt] = WhS[(((kc * 4 + ktl) * 4) + wn * 2 + nt) * 32 + lane];
#pragma unroll
                    for (int mt = 0; mt < 2; mt++) {
                        int r = wm * 32 + mt * 16 + (lane & 15);
                        int ch = ktl * 16 + ((lane >> 4) << 3);
                        uint32_t afr[4];
                        ldsm_x4(afr[0], afr[1], afr[2], afr[3],
                                s2u(A + swz(r * 128 + ch * 2)));
                        mma16816(acc[mt][0], afr, bfr[0]);
                        mma16816(acc[mt][1], afr, bfr[1]);
                    }
                }
                if (kc + 3 < 16) { poll(kc + 3); load_chunk(kc + 3); }
            }
            // write z tile to smem and exchange
#pragma unroll
            for (int mt = 0; mt < 2; mt++) {
                int r = wm * 32 + mt * 16 + (lane >> 2);
#pragma unroll
                for (int nt = 0; nt < 2; nt++) {
                    int cl = (wn * 2 + nt) * 8 + (lane & 3) * 2;
                    zs[r * 32 + cl]           = acc[mt][nt][0];
                    zs[r * 32 + cl + 1]       = acc[mt][nt][1];
                    zs[(r + 8) * 32 + cl]     = acc[mt][nt][2];
                    zs[(r + 8) * 32 + cl + 1] = acc[mt][nt][3];
                }
            }
            __syncthreads();
        }

        // gate math + h write
        __nv_bfloat16* hdst = g_h[t & 1];
#pragma unroll
        for (int i = 0; i < 4; i++) {
            int cell = tid + i * 256;
            int b = cell >> 3, jl = cell & 7;
            float zi = zx[i][0], zf = zx[i][1], zg = zx[i][2], zo = zx[i][3];
            if (t > 0) {
                zi += zs[b * 32 + 0 + jl];
                zf += zs[b * 32 + 8 + jl];
                zg += zs[b * 32 + 16 + jl];
                zo += zs[b * 32 + 24 + jl];
            }
            float it = fast_sigmoid(zi);
            float ft = fast_sigmoid(zf);
            float gt = fast_tanh(zg);
            float ot = fast_sigmoid(zo);
            cst[i] = ft * cst[i] + it * gt;
            float hh = ot * fast_tanh(cst[i]);
            if (!last) hdst[(size_t)b * H_ + ct * 8 + jl] = __float2bfloat16(hh);
            else       g_hT[(size_t)b * H_ + ct * 8 + jl] = hh;
        }

        if (!last) {
            __threadfence();
            __syncthreads();      // all h stores fenced + zs reads done before reuse
            if (tid == 0) atomicAdd(&g_gcnt[ct >> 3], 1u);
            // prefetch Zx for step t+1 (overlaps with next step's polls)
#pragma unroll
            for (int i = 0; i < 4; i++) {
                int cell = tid + i * 256;
                int b = cell >> 3, jl = cell & 7;
                const float* zp = &g_Zx[(size_t)((t + 1) * B_ + b) * NCOLS + ct * 8 + jl];
                zx[i][0] = __ldcs(zp); zx[i][1] = __ldcs(zp + 1024);
                zx[i][2] = __ldcs(zp + 2048); zx[i][3] = __ldcs(zp + 3072);
            }
        }
    }
}

// ---------------- Phase C: logits + log_softmax ----------------
__global__ void __launch_bounds__(256) k_logits(const float* __restrict__ Wout,
                                                const float* __restrict__ bout,
                                                float* __restrict__ out) {
    __shared__ float hs[1024];
    __shared__ float ls[1024];
    __shared__ float red[16];
    const int b = blockIdx.x, tid = threadIdx.x, lane = tid & 31, w = tid >> 5;
    for (int i = tid; i < 1024; i += 256) hs[i] = g_hT[(size_t)b * H_ + i];
    __syncthreads();
    for (int k = 0; k < 4; k++) {
        int o = tid + k * 256;
        const float4* wr = reinterpret_cast<const float4*>(Wout + (size_t)o * H_);
        float s = 0.f;
#pragma unroll 4
        for (int h4 = 0; h4 < 256; h4++) {
            float4 wv = wr[h4];
            s += hs[h4 * 4 + 0] * wv.x + hs[h4 * 4 + 1] * wv.y +
                 hs[h4 * 4 + 2] * wv.z + hs[h4 * 4 + 3] * wv.w;
        }
        ls[o] = s + bout[o];
    }
    __syncthreads();
    float lm = -1e30f;
    for (int i = tid; i < 1024; i += 256) lm = fmaxf(lm, ls[i]);
#pragma unroll
    for (int off = 16; off; off >>= 1) lm = fmaxf(lm, __shfl_xor_sync(0xffffffffu, lm, off));
    if (lane == 0) red[w] = lm;
    __syncthreads();
    float m = red[0];
#pragma unroll
    for (int j = 1; j < 8; j++) m = fmaxf(m, red[j]);
    float se = 0.f;
    for (int i = tid; i < 1024; i += 256) se += expf(ls[i] - m);
#pragma unroll
    for (int off = 16; off; off >>= 1) se += __shfl_xor_sync(0xffffffffu, se, off);
    if (lane == 0) red[8 + w] = se;
    __syncthreads();
    float tot = 0.f;
#pragma unroll
    for (int j = 0; j < 8; j++) tot += red[8 + j];
    float lse = logf(tot);
    for (int i = tid; i < 1024; i += 256)
        out[(size_t)b * O_ + i] = ls[i] - m - lse;
}

// ---------------- launch ----------------
extern "C" void kernel_launch(void* const* d_in, const int* in_sizes, int n_in,
                              void* d_out, int out_size) {
    const float* x    = (const float*)d_in[0];
    const float* Wf   = (const float*)d_in[1];
    const float* bf   = (const float*)d_in[2];
    const float* Wi   = (const float*)d_in[3];
    const float* bi   = (const float*)d_in[4];
    const float* Wg   = (const float*)d_in[5];
    const float* bg   = (const float*)d_in[6];
    const float* Wo   = (const float*)d_in[7];
    const float* bo   = (const float*)d_in[8];
    const float* Wout = (const float*)d_in[9];
    const float* bout = (const float*)d_in[10];
    float* out = (float*)d_out;

    cudaFuncSetAttribute(k_gemmA, cudaFuncAttributeMaxDynamicSharedMemorySize, 98304);
    cudaFuncSetAttribute(k_lstm,  cudaFuncAttributeMaxDynamicSharedMemorySize, 147456);

    // Order chosen so k_gemmA is the 4th launch (the one ncu profiles).
    k_cvt_x<<<(MROWS * D_ / 4 + 511) / 512, 512>>>(x);
    k_pack_wx<<<(32 * 64 * 16 * 32) / 256, 256>>>(Wf, Wi, Wg, Wo);
    k_pack_b<<<NCOLS / 256, 256>>>(bf, bi, bg, bo);
    dim3 gA(32, 256);
    k_gemmA<<<gA, 256, 98304>>>();
    k_pack_wh<<<(128 * 64 * 4 * 32) / 256, 256>>>(Wf, Wi, Wg, Wo);
    k_epoch<<<1, 32>>>();
    k_lstm<<<128, 256, 147456>>>();
    k_logits<<<B_, 256>>>(Wout, bout, out);
}